// round 1
// baseline (speedup 1.0000x reference)
#include <cuda_runtime.h>
#include <cstdint>

#define NIMG 256
#define IMGS_PER_BLK 4

// Layer configs:
//   cin:   {3, 344, 352, 686, 679, 1246}   cout: {344, 352, 686, 679, 1246, 973}
//   conv-space H=W: {32,32,16,16,8,8}, pool after layers 1,3,5
//   input words (padded to x4): {4,12,12,24,24,40}, output words: {12,12,24,24,40,32}

__device__ uint32_t g_bufA[(size_t)NIMG * 32 * 32 * 12];
__device__ uint32_t g_bufB[(size_t)NIMG * 32 * 32 * 12];
__device__ uint32_t g_wpk[949248];       // packed weights, all layers
__device__ float2   g_th[4608];          // per-channel (scale, bias-m*scale), padded
__device__ uint32_t g_fcpk[10 * 16 * 32];

// ---------------------------------------------------------------------------
// Pack input x [256,3,32,32] -> bits [n][h][w][4 words] (3 bits in word0)
__global__ void pack_x_kernel(const float* __restrict__ x, uint32_t* __restrict__ dst)
{
    int idx = blockIdx.x * blockDim.x + threadIdx.x;   // n*1024 + pix
    if (idx >= NIMG * 1024) return;
    int n = idx >> 10, pix = idx & 1023;
    const float* xb = x + (size_t)n * 3 * 1024 + pix;
    uint32_t w = 0;
    if (xb[0]    > 0.f) w |= 1u;
    if (xb[1024] > 0.f) w |= 2u;
    if (xb[2048] > 0.f) w |= 4u;
    uint32_t* d = dst + (size_t)idx * 4;
    d[0] = w; d[1] = 0u; d[2] = 0u; d[3] = 0u;
}

// Pack conv weights [Co][Ci][3][3] -> [wi][tap][32co][WINP words], zero-padded
__global__ void pack_w_kernel(const float* __restrict__ w, uint32_t* __restrict__ dst,
                              int Co, int Ci, int WINP, int nCoP)
{
    int idx = blockIdx.x * blockDim.x + threadIdx.x;   // co_p*9 + tap
    if (idx >= nCoP * 9) return;
    int tap = idx % 9;
    int co  = idx / 9;
    int wi  = co >> 5, cl = co & 31;
    const float* ws = w + ((size_t)co * Ci) * 9 + tap;
    for (int q = 0; q < WINP; ++q) {
        uint32_t bits = 0;
        if (co < Co) {
            int cbase = q * 32;
            for (int b = 0; b < 32; ++b) {
                int ci = cbase + b;
                if (ci < Ci && ws[(size_t)ci * 9] > 0.f) bits |= 1u << b;
            }
        }
        dst[(((size_t)wi * 9 + tap) * 32 + cl) * WINP + q] = bits;
    }
}

// Pack BN threshold: p is [4][C] = (gamma, beta, mean, var)
__global__ void pack_th_kernel(const float* __restrict__ p, float2* __restrict__ th,
                               int Co, int nCoP)
{
    int c = blockIdx.x * blockDim.x + threadIdx.x;
    if (c >= nCoP) return;
    float2 t;
    if (c < Co) {
        float gg = p[c], bb = p[Co + c], mm = p[2 * Co + c], vv = p[3 * Co + c];
        float sc = gg * rsqrtf(vv + 1e-5f);
        t.x = sc; t.y = bb - mm * sc;
    } else {
        t.x = 0.f; t.y = -1.f;   // padded channel -> bit 0
    }
    th[c] = t;
}

// Pack FC weights [10][15568] (idx = c*16 + s) -> [o][s][32 words over c]
__global__ void pack_fc_kernel(const float* __restrict__ fcw, uint32_t* __restrict__ dst)
{
    int idx = blockIdx.x * blockDim.x + threadIdx.x;   // (o*16+s)*32 + wi
    if (idx >= 10 * 16 * 32) return;
    int wi = idx & 31; int r = idx >> 5;
    int s = r & 15; int o = r >> 4;
    uint32_t bits = 0;
    for (int b = 0; b < 32; ++b) {
        int c = wi * 32 + b;
        if (c < 973 && fcw[(size_t)o * 15568 + c * 16 + s] > 0.f) bits |= 1u << b;
    }
    dst[idx] = bits;
}

// ---------------------------------------------------------------------------
// Binary conv: 3x3, pad 1, XNOR-popcount + BN threshold -> packed output bits.
// Block: 256 threads = 64 pixels (8x8 tile) x 4 groups of 8 output channels.
// gridDim = (tiles, WOUTP (one 32-ch word each), NIMG/IMGS_PER_BLK)
template <int WINP>
__global__ void __launch_bounds__(256)
bconv_kernel(const uint32_t* __restrict__ in, uint8_t* __restrict__ out,
             const uint32_t* __restrict__ wpk, const float2* __restrict__ th,
             int H, int W, int Cin, int WOUTP, int tilesX)
{
    extern __shared__ uint32_t sm[];
    uint32_t* sw = sm;                   // 9*32*WINP weight words
    uint32_t* sx = sm + 9 * 32 * WINP;   // 10*10*WINP patch words
    const int tid = threadIdx.x;
    const int wi = blockIdx.y;
    const int x0 = (blockIdx.x % tilesX) * 8;
    const int y0 = (blockIdx.x / tilesX) * 8;

    const uint32_t* wsrc = wpk + (size_t)wi * (9 * 32 * WINP);
    for (int i = tid; i < 9 * 32 * WINP; i += 256) sw[i] = wsrc[i];

    const int g  = tid >> 6;
    const int p  = tid & 63;
    const int py = p >> 3;
    const int px = p & 7;

    float2 t8[8];
#pragma unroll
    for (int j = 0; j < 8; ++j) t8[j] = th[wi * 32 + g * 8 + j];

    for (int it = 0; it < IMGS_PER_BLK; ++it) {
        const int n = blockIdx.z * IMGS_PER_BLK + it;
        __syncthreads();
        const uint32_t* ibase = in + (size_t)n * H * W * WINP;
        for (int i = tid; i < 100 * WINP; i += 256) {
            const int w  = i % WINP;
            const int pp = i / WINP;
            const int iy = y0 + pp / 10 - 1;
            const int ix = x0 + pp % 10 - 1;
            uint32_t v = 0u;
            if (iy >= 0 && iy < H && ix >= 0 && ix < W)
                v = ibase[((size_t)iy * W + ix) * WINP + w];
            sx[i] = v;
        }
        __syncthreads();

        int D[8];
#pragma unroll
        for (int j = 0; j < 8; ++j) D[j] = 0;
        int nv = 0;
#pragma unroll 1
        for (int ky = 0; ky < 3; ++ky) {
            const int iy = y0 + py + ky - 1;
#pragma unroll 1
            for (int kx = 0; kx < 3; ++kx) {
                const int ix = x0 + px + kx - 1;
                if (iy < 0 || iy >= H || ix < 0 || ix >= W) continue;
                ++nv;
                const uint4* xp = (const uint4*)&sx[((py + ky) * 10 + (px + kx)) * WINP];
                const uint32_t* wb = &sw[((ky * 3 + kx) * 32 + g * 8) * WINP];
#pragma unroll
                for (int q = 0; q < WINP / 4; ++q) {
                    const uint4 xv = xp[q];
#pragma unroll
                    for (int j = 0; j < 8; ++j) {
                        const uint4 wv = *(const uint4*)(wb + j * WINP + q * 4);
                        D[j] += __popc(xv.x ^ wv.x) + __popc(xv.y ^ wv.y)
                              + __popc(xv.z ^ wv.z) + __popc(xv.w ^ wv.w);
                    }
                }
            }
        }
        unsigned bytev = 0u;
        const float fnv = (float)(nv * Cin);
#pragma unroll
        for (int j = 0; j < 8; ++j) {
            const float dot = fnv - 2.0f * (float)D[j];
            if (fmaf(dot, t8[j].x, t8[j].y) > 0.0f) bytev |= 1u << j;
        }
        out[(((size_t)n * H * W + (size_t)(y0 + py) * W + (x0 + px)) * WOUTP + wi) * 4 + g]
            = (uint8_t)bytev;
    }
}

// Maxpool 2x2 on packed bits == bitwise OR (BN scale > 0, monotone)
__global__ void pool_kernel(const uint32_t* __restrict__ in, uint32_t* __restrict__ out,
                            int Ho, int Wo, int WORDS, int total)
{
    int idx = blockIdx.x * blockDim.x + threadIdx.x;
    if (idx >= total) return;
    int w = idx % WORDS; int r = idx / WORDS;
    int xo = r % Wo; r /= Wo;
    int yo = r % Ho; int n = r / Ho;
    const int Wi = Wo * 2;
    size_t base = (((size_t)n * (Ho * 2) + yo * 2) * Wi + xo * 2) * WORDS + w;
    size_t rs = (size_t)Wi * WORDS;
    out[idx] = in[base] | in[base + WORDS] | in[base + rs] | in[base + rs + WORDS];
}

// Binary FC: out[n][o] = 15568 - 2*popc(x ^ w) + fcb[o]
__global__ void fc_kernel(const uint32_t* __restrict__ xb, const uint32_t* __restrict__ wb,
                          const float* __restrict__ fcb, float* __restrict__ out)
{
    int t = blockIdx.x * blockDim.x + threadIdx.x;
    if (t >= NIMG * 10) return;
    int n = t / 10, o = t - n * 10;
    const uint4* xa = (const uint4*)(xb + (size_t)n * 512);
    const uint4* wa = (const uint4*)(wb + (size_t)o * 512);
    int D = 0;
#pragma unroll 8
    for (int i = 0; i < 128; ++i) {
        uint4 a = xa[i], b = wa[i];
        D += __popc(a.x ^ b.x) + __popc(a.y ^ b.y) + __popc(a.z ^ b.z) + __popc(a.w ^ b.w);
    }
    out[t] = (float)(15568 - 2 * D) + fcb[o];
}

// ---------------------------------------------------------------------------
extern "C" void kernel_launch(void* const* d_in, const int* in_sizes, int n_in,
                              void* d_out, int out_size)
{
    static const int s_cin[6]   = {3, 344, 352, 686, 679, 1246};
    static const int s_cout[6]  = {344, 352, 686, 679, 1246, 973};
    static const int s_H[6]     = {32, 32, 16, 16, 8, 8};
    static const int s_winp[6]  = {4, 12, 12, 24, 24, 40};
    static const int s_woutp[6] = {12, 12, 24, 24, 40, 32};
    static const size_t s_woff[6] = {0, 13824, 55296, 138240, 304128, 580608};
    static const size_t s_toff[6] = {0, 384, 768, 1536, 2304, 3584};

    // Locate inputs by unique element counts (robust to d_in ordering)
    const long long szw[6] = {344LL*3*9, 352LL*344*9, 686LL*352*9,
                              679LL*686*9, 1246LL*679*9, 973LL*1246*9};
    const long long szp[6] = {4LL*344, 4LL*352, 4LL*686, 4LL*679, 4LL*1246, 4LL*973};
    auto find = [&](long long s) -> const void* {
        for (int i = 0; i < n_in; ++i)
            if ((long long)in_sizes[i] == s) return d_in[i];
        return (const void*)0;
    };
    const float* x   = (const float*)find(256LL * 3 * 32 * 32);
    const float* fcw = (const float*)find(10LL * 15568);
    const float* fcb = (const float*)find(10);
    const float* w[6]; const float* p[6];
    for (int i = 0; i < 6; ++i) {
        w[i] = (const float*)find(szw[i]);
        p[i] = (const float*)find(szp[i]);
    }
    if (!x || !fcw || !fcb) return;

    void *pA, *pB, *pW, *pT, *pF;
    cudaGetSymbolAddress(&pA, g_bufA);
    cudaGetSymbolAddress(&pB, g_bufB);
    cudaGetSymbolAddress(&pW, g_wpk);
    cudaGetSymbolAddress(&pT, g_th);
    cudaGetSymbolAddress(&pF, g_fcpk);
    uint32_t* bufA = (uint32_t*)pA;
    uint32_t* bufB = (uint32_t*)pB;
    uint32_t* wpk  = (uint32_t*)pW;
    float2*   th   = (float2*)pT;
    uint32_t* fcpk = (uint32_t*)pF;

    cudaFuncSetAttribute(bconv_kernel<40>, cudaFuncAttributeMaxDynamicSharedMemorySize, 1552 * 40);
    cudaFuncSetAttribute(bconv_kernel<24>, cudaFuncAttributeMaxDynamicSharedMemorySize, 1552 * 24);

    // --- pack phase ---
    pack_x_kernel<<<(NIMG * 1024 + 255) / 256, 256>>>(x, bufA);
    for (int l = 0; l < 6; ++l) {
        int nCoP = s_woutp[l] * 32;
        pack_w_kernel<<<(nCoP * 9 + 255) / 256, 256>>>(w[l], wpk + s_woff[l],
                                                       s_cout[l], s_cin[l], s_winp[l], nCoP);
        pack_th_kernel<<<(nCoP + 255) / 256, 256>>>(p[l], th + s_toff[l], s_cout[l], nCoP);
    }
    pack_fc_kernel<<<20, 256>>>(fcw, fcpk);

    // --- conv stack ---
    auto conv = [&](int l, const uint32_t* src, uint32_t* dst) {
        int H = s_H[l], W = H;
        int WINP = s_winp[l], WOUTP = s_woutp[l], Cin = s_cin[l];
        int tilesX = W / 8;
        dim3 grid((unsigned)((H / 8) * (W / 8)), (unsigned)WOUTP, (unsigned)(NIMG / IMGS_PER_BLK));
        size_t smem = (size_t)1552 * WINP;
        uint8_t* ob = (uint8_t*)dst;
        const uint32_t* wb = wpk + s_woff[l];
        const float2* tb = th + s_toff[l];
        switch (WINP) {
            case 4:  bconv_kernel<4><<<grid, 256, smem>>>(src, ob, wb, tb, H, W, Cin, WOUTP, tilesX); break;
            case 12: bconv_kernel<12><<<grid, 256, smem>>>(src, ob, wb, tb, H, W, Cin, WOUTP, tilesX); break;
            case 24: bconv_kernel<24><<<grid, 256, smem>>>(src, ob, wb, tb, H, W, Cin, WOUTP, tilesX); break;
            case 40: bconv_kernel<40><<<grid, 256, smem>>>(src, ob, wb, tb, H, W, Cin, WOUTP, tilesX); break;
        }
    };

    conv(0, bufA, bufB);                                    // [32,32,12] bits in B
    conv(1, bufB, bufA);                                    // conv-space [32,32,12] in A
    {   int tot = NIMG * 16 * 16 * 12;
        pool_kernel<<<(tot + 255) / 256, 256>>>(bufA, bufB, 16, 16, 12, tot); }  // B: [16,16,12]
    conv(2, bufB, bufA);                                    // A: [16,16,24]
    conv(3, bufA, bufB);                                    // conv-space [16,16,24] in B
    {   int tot = NIMG * 8 * 8 * 24;
        pool_kernel<<<(tot + 255) / 256, 256>>>(bufB, bufA, 8, 8, 24, tot); }    // A: [8,8,24]
    conv(4, bufA, bufB);                                    // B: [8,8,40]
    conv(5, bufB, bufA);                                    // conv-space [8,8,32] in A
    {   int tot = NIMG * 4 * 4 * 32;
        pool_kernel<<<(tot + 255) / 256, 256>>>(bufA, bufB, 4, 4, 32, tot); }    // B: [4,4,32]

    // --- FC ---
    fc_kernel<<<10, 256>>>(bufB, fcpk, fcb, (float*)d_out);
}

// round 2
// speedup vs baseline: 1.1080x; 1.1080x over previous
#include <cuda_runtime.h>
#include <cstdint>

#define NIMG 256
#define IMGS_PER_BLK 8

// Layer configs:
//   cin:   {3, 344, 352, 686, 679, 1246}   cout: {344, 352, 686, 679, 1246, 973}
//   conv-space H=W: {32,32,16,16,8,8}, pool after layers 1,3,5
//   input words (padded to x4): {4,12,12,24,24,40}, output words: {12,12,24,24,40,32}

__device__ uint32_t g_bufA[(size_t)NIMG * 32 * 32 * 12];
__device__ uint32_t g_bufB[(size_t)NIMG * 32 * 32 * 12];
__device__ uint32_t g_wpk[949248];       // packed weights, all layers
__device__ float2   g_th[4608];          // per-channel (scale, beta - mean*scale), padded
__device__ uint32_t g_fcpk[10 * 16 * 32];

// ---------------------------------------------------------------------------
// Pack input x [256,3,32,32] -> bits [n][h][w][4 words] (3 bits in word0)
__global__ void pack_x_kernel(const float* __restrict__ x, uint32_t* __restrict__ dst)
{
    int idx = blockIdx.x * blockDim.x + threadIdx.x;   // n*1024 + pix
    if (idx >= NIMG * 1024) return;
    int n = idx >> 10, pix = idx & 1023;
    const float* xb = x + (size_t)n * 3 * 1024 + pix;
    uint32_t w = 0;
    if (xb[0]    > 0.f) w |= 1u;
    if (xb[1024] > 0.f) w |= 2u;
    if (xb[2048] > 0.f) w |= 4u;
    uint32_t* d = dst + (size_t)idx * 4;
    d[0] = w; d[1] = 0u; d[2] = 0u; d[3] = 0u;
}

// ---------------------------------------------------------------------------
// Pack ALL conv weights in one launch: one WARP per packed word (ballot).
// dst layout per layer: [wi][tap][32 co][WINP words]
__global__ void pack_w_all_kernel(const float* __restrict__ w0, const float* __restrict__ w1,
                                  const float* __restrict__ w2, const float* __restrict__ w3,
                                  const float* __restrict__ w4, const float* __restrict__ w5,
                                  uint32_t* __restrict__ dst)
{
    const int cum[7]  = {0, 13824, 55296, 138240, 304128, 580608, 949248};
    const int cin[6]  = {3, 344, 352, 686, 679, 1246};
    const int cout[6] = {344, 352, 686, 679, 1246, 973};
    const int winp[6] = {4, 12, 12, 24, 24, 40};

    int warp = (blockIdx.x * blockDim.x + threadIdx.x) >> 5;
    int lane = threadIdx.x & 31;
    if (warp >= 949248) return;

    int l = 0;
#pragma unroll
    for (int i = 1; i < 6; ++i) if (warp >= cum[i]) l = i;

    const float* wsrc = (l == 0) ? w0 : (l == 1) ? w1 : (l == 2) ? w2
                       : (l == 3) ? w3 : (l == 4) ? w4 : w5;
    const int Ci = cin[l], Co = cout[l], WINP = winp[l];

    int widx = warp - cum[l];
    int q   = widx % WINP;  widx /= WINP;
    int cl  = widx & 31;    widx >>= 5;
    int tap = widx % 9;
    int wi  = widx / 9;
    int co  = wi * 32 + cl;
    int ci  = q * 32 + lane;

    float v = 0.f;
    if (co < Co && ci < Ci)
        v = wsrc[((size_t)co * Ci + ci) * 9 + tap];
    uint32_t bits = __ballot_sync(0xFFFFFFFFu, v > 0.f);
    if (lane == 0) dst[warp] = bits;
}

// Pack ALL BN thresholds in one launch. p per layer is [4][C] = (g, b, m, v)
__global__ void pack_th_all_kernel(const float* __restrict__ p0, const float* __restrict__ p1,
                                   const float* __restrict__ p2, const float* __restrict__ p3,
                                   const float* __restrict__ p4, const float* __restrict__ p5,
                                   float2* __restrict__ th)
{
    const int cum[7]  = {0, 384, 768, 1536, 2304, 3584, 4608};
    const int cout[6] = {344, 352, 686, 679, 1246, 973};
    int idx = blockIdx.x * blockDim.x + threadIdx.x;
    if (idx >= 4608) return;
    int l = 0;
#pragma unroll
    for (int i = 1; i < 6; ++i) if (idx >= cum[i]) l = i;
    const float* p = (l == 0) ? p0 : (l == 1) ? p1 : (l == 2) ? p2
                    : (l == 3) ? p3 : (l == 4) ? p4 : p5;
    int c = idx - cum[l];
    int Co = cout[l];
    float2 t;
    if (c < Co) {
        float gg = p[c], bb = p[Co + c], mm = p[2 * Co + c], vv = p[3 * Co + c];
        float sc = gg * rsqrtf(vv + 1e-5f);
        t.x = sc; t.y = bb - mm * sc;
    } else {
        t.x = 0.f; t.y = -1.f;   // padded channel -> bit 0
    }
    th[idx] = t;
}

// Pack FC weights [10][15568] (idx = c*16 + s) -> [o][s][32 words over c], warp ballot
__global__ void pack_fc_kernel(const float* __restrict__ fcw, uint32_t* __restrict__ dst)
{
    int warp = (blockIdx.x * blockDim.x + threadIdx.x) >> 5;
    int lane = threadIdx.x & 31;
    if (warp >= 10 * 16 * 32) return;
    int wi = warp & 31; int r = warp >> 5;
    int s = r & 15; int o = r >> 4;
    int c = wi * 32 + lane;
    float v = (c < 973) ? fcw[(size_t)o * 15568 + c * 16 + s] : 0.f;
    uint32_t bits = __ballot_sync(0xFFFFFFFFu, v > 0.f);
    if (lane == 0) dst[warp] = bits;
}

// ---------------------------------------------------------------------------
// Binary conv: 3x3, pad 1, XNOR-popcount + BN threshold -> packed output bits.
// Block: 256 threads = 64 pixels (8x8 tile) x 4 groups of 8 output channels.
// gridDim = (tiles, WOUTP (one 32-ch word each), NIMG/IMGS_PER_BLK)
template <int WINP>
__global__ void __launch_bounds__(256)
bconv_kernel(const uint32_t* __restrict__ in, uint8_t* __restrict__ out,
             const uint32_t* __restrict__ wpk, const float2* __restrict__ th,
             int H, int W, int Cin, int WOUTP, int tilesX)
{
    extern __shared__ uint32_t sm[];
    uint32_t* sw = sm;                   // 9*32*WINP weight words
    uint32_t* sx = sm + 9 * 32 * WINP;   // 10*10*WINP patch words
    const int tid = threadIdx.x;
    const int wi = blockIdx.y;
    const int x0 = (blockIdx.x % tilesX) * 8;
    const int y0 = (blockIdx.x / tilesX) * 8;

    const uint32_t* wsrc = wpk + (size_t)wi * (9 * 32 * WINP);
    for (int i = tid; i < 9 * 32 * WINP; i += 256) sw[i] = wsrc[i];

    const int g  = tid >> 6;
    const int p  = tid & 63;
    const int py = p >> 3;
    const int px = p & 7;

    float2 t8[8];
#pragma unroll
    for (int j = 0; j < 8; ++j) t8[j] = th[wi * 32 + g * 8 + j];

    for (int it = 0; it < IMGS_PER_BLK; ++it) {
        const int n = blockIdx.z * IMGS_PER_BLK + it;
        __syncthreads();
        const uint32_t* ibase = in + (size_t)n * H * W * WINP;
        for (int i = tid; i < 100 * WINP; i += 256) {
            const int w  = i % WINP;
            const int pp = i / WINP;
            const int iy = y0 + pp / 10 - 1;
            const int ix = x0 + pp % 10 - 1;
            uint32_t v = 0u;
            if (iy >= 0 && iy < H && ix >= 0 && ix < W)
                v = ibase[((size_t)iy * W + ix) * WINP + w];
            sx[i] = v;
        }
        __syncthreads();

        int D[8];
#pragma unroll
        for (int j = 0; j < 8; ++j) D[j] = 0;
        int nv = 0;
#pragma unroll 1
        for (int ky = 0; ky < 3; ++ky) {
            const int iy = y0 + py + ky - 1;
#pragma unroll 1
            for (int kx = 0; kx < 3; ++kx) {
                const int ix = x0 + px + kx - 1;
                if (iy < 0 || iy >= H || ix < 0 || ix >= W) continue;
                ++nv;
                const uint4* xp = (const uint4*)&sx[((py + ky) * 10 + (px + kx)) * WINP];
                const uint32_t* wb = &sw[((ky * 3 + kx) * 32 + g * 8) * WINP];
#pragma unroll
                for (int q = 0; q < WINP / 4; ++q) {
                    const uint4 xv = xp[q];
#pragma unroll
                    for (int j = 0; j < 8; ++j) {
                        const uint4 wv = *(const uint4*)(wb + j * WINP + q * 4);
                        D[j] += (__popc(xv.x ^ wv.x) + __popc(xv.y ^ wv.y))
                              + (__popc(xv.z ^ wv.z) + __popc(xv.w ^ wv.w));
                    }
                }
            }
        }
        unsigned bytev = 0u;
        const float fnv = (float)(nv * Cin);
#pragma unroll
        for (int j = 0; j < 8; ++j) {
            const float dot = fnv - 2.0f * (float)D[j];
            if (fmaf(dot, t8[j].x, t8[j].y) > 0.0f) bytev |= 1u << j;
        }
        out[(((size_t)n * H * W + (size_t)(y0 + py) * W + (x0 + px)) * WOUTP + wi) * 4 + g]
            = (uint8_t)bytev;
    }
}

// Maxpool 2x2 on packed bits == bitwise OR (BN scale > 0, monotone)
__global__ void pool_kernel(const uint32_t* __restrict__ in, uint32_t* __restrict__ out,
                            int Ho, int Wo, int WORDS, int total)
{
    int idx = blockIdx.x * blockDim.x + threadIdx.x;
    if (idx >= total) return;
    int w = idx % WORDS; int r = idx / WORDS;
    int xo = r % Wo; r /= Wo;
    int yo = r % Ho; int n = r / Ho;
    const int Wi = Wo * 2;
    size_t base = (((size_t)n * (Ho * 2) + yo * 2) * Wi + xo * 2) * WORDS + w;
    size_t rs = (size_t)Wi * WORDS;
    out[idx] = in[base] | in[base + WORDS] | in[base + rs] | in[base + rs + WORDS];
}

// Binary FC: out[n][o] = 15568 - 2*popc(x ^ w) + fcb[o]
__global__ void fc_kernel(const uint32_t* __restrict__ xb, const uint32_t* __restrict__ wb,
                          const float* __restrict__ fcb, float* __restrict__ out)
{
    int t = blockIdx.x * blockDim.x + threadIdx.x;
    if (t >= NIMG * 10) return;
    int n = t / 10, o = t - n * 10;
    const uint4* xa = (const uint4*)(xb + (size_t)n * 512);
    const uint4* wa = (const uint4*)(wb + (size_t)o * 512);
    int D = 0;
#pragma unroll 8
    for (int i = 0; i < 128; ++i) {
        uint4 a = xa[i], b = wa[i];
        D += __popc(a.x ^ b.x) + __popc(a.y ^ b.y) + __popc(a.z ^ b.z) + __popc(a.w ^ b.w);
    }
    out[t] = (float)(15568 - 2 * D) + fcb[o];
}

// ---------------------------------------------------------------------------
extern "C" void kernel_launch(void* const* d_in, const int* in_sizes, int n_in,
                              void* d_out, int out_size)
{
    static const int s_cin[6]   = {3, 344, 352, 686, 679, 1246};
    static const int s_H[6]     = {32, 32, 16, 16, 8, 8};
    static const int s_winp[6]  = {4, 12, 12, 24, 24, 40};
    static const int s_woutp[6] = {12, 12, 24, 24, 40, 32};
    static const size_t s_woff[6] = {0, 13824, 55296, 138240, 304128, 580608};
    static const size_t s_toff[6] = {0, 384, 768, 1536, 2304, 3584};

    // Locate inputs by unique element counts (robust to d_in ordering)
    const long long szw[6] = {344LL*3*9, 352LL*344*9, 686LL*352*9,
                              679LL*686*9, 1246LL*679*9, 973LL*1246*9};
    const long long szp[6] = {4LL*344, 4LL*352, 4LL*686, 4LL*679, 4LL*1246, 4LL*973};
    auto find = [&](long long s) -> const void* {
        for (int i = 0; i < n_in; ++i)
            if ((long long)in_sizes[i] == s) return d_in[i];
        return (const void*)0;
    };
    const float* x   = (const float*)find(256LL * 3 * 32 * 32);
    const float* fcw = (const float*)find(10LL * 15568);
    const float* fcb = (const float*)find(10);
    const float* w[6]; const float* p[6];
    for (int i = 0; i < 6; ++i) {
        w[i] = (const float*)find(szw[i]);
        p[i] = (const float*)find(szp[i]);
    }
    if (!x || !fcw || !fcb) return;

    void *pA, *pB, *pW, *pT, *pF;
    cudaGetSymbolAddress(&pA, g_bufA);
    cudaGetSymbolAddress(&pB, g_bufB);
    cudaGetSymbolAddress(&pW, g_wpk);
    cudaGetSymbolAddress(&pT, g_th);
    cudaGetSymbolAddress(&pF, g_fcpk);
    uint32_t* bufA = (uint32_t*)pA;
    uint32_t* bufB = (uint32_t*)pB;
    uint32_t* wpk  = (uint32_t*)pW;
    float2*   th   = (float2*)pT;
    uint32_t* fcpk = (uint32_t*)pF;

    cudaFuncSetAttribute(bconv_kernel<40>, cudaFuncAttributeMaxDynamicSharedMemorySize, 1552 * 40);
    cudaFuncSetAttribute(bconv_kernel<24>, cudaFuncAttributeMaxDynamicSharedMemorySize, 1552 * 24);

    // --- pack phase (4 launches; ncu -s 5 then lands on conv layer 1) ---
    pack_x_kernel<<<(NIMG * 1024 + 255) / 256, 256>>>(x, bufA);
    pack_w_all_kernel<<<(949248 * 32 + 255) / 256, 256>>>(w[0], w[1], w[2], w[3], w[4], w[5], wpk);
    pack_th_all_kernel<<<(4608 + 255) / 256, 256>>>(p[0], p[1], p[2], p[3], p[4], p[5], th);
    pack_fc_kernel<<<(10 * 16 * 32 * 32 + 255) / 256, 256>>>(fcw, fcpk);

    // --- conv stack ---
    auto conv = [&](int l, const uint32_t* src, uint32_t* dst) {
        int H = s_H[l], W = H;
        int WINP = s_winp[l], WOUTP = s_woutp[l], Cin = s_cin[l];
        int tilesX = (W + 7) / 8;
        dim3 grid((unsigned)(((H + 7) / 8) * tilesX), (unsigned)WOUTP,
                  (unsigned)(NIMG / IMGS_PER_BLK));
        size_t smem = (size_t)1552 * WINP;
        uint8_t* ob = (uint8_t*)dst;
        const uint32_t* wb = wpk + s_woff[l];
        const float2* tb = th + s_toff[l];
        switch (WINP) {
            case 4:  bconv_kernel<4><<<grid, 256, smem>>>(src, ob, wb, tb, H, W, Cin, WOUTP, tilesX); break;
            case 12: bconv_kernel<12><<<grid, 256, smem>>>(src, ob, wb, tb, H, W, Cin, WOUTP, tilesX); break;
            case 24: bconv_kernel<24><<<grid, 256, smem>>>(src, ob, wb, tb, H, W, Cin, WOUTP, tilesX); break;
            case 40: bconv_kernel<40><<<grid, 256, smem>>>(src, ob, wb, tb, H, W, Cin, WOUTP, tilesX); break;
        }
    };

    conv(0, bufA, bufB);                                    // B: [32,32,12]
    conv(1, bufB, bufA);                                    // A: conv-space [32,32,12]
    {   int tot = NIMG * 16 * 16 * 12;
        pool_kernel<<<(tot + 255) / 256, 256>>>(bufA, bufB, 16, 16, 12, tot); }  // B: [16,16,12]
    conv(2, bufB, bufA);                                    // A: [16,16,24]
    conv(3, bufA, bufB);                                    // B: conv-space [16,16,24]
    {   int tot = NIMG * 8 * 8 * 24;
        pool_kernel<<<(tot + 255) / 256, 256>>>(bufB, bufA, 8, 8, 24, tot); }    // A: [8,8,24]
    conv(4, bufA, bufB);                                    // B: [8,8,40]
    conv(5, bufB, bufA);                                    // A: conv-space [8,8,32]
    {   int tot = NIMG * 4 * 4 * 32;
        pool_kernel<<<(tot + 255) / 256, 256>>>(bufA, bufB, 4, 4, 32, tot); }    // B: [4,4,32]

    // --- FC ---
    fc_kernel<<<10, 256>>>(bufB, fcpk, fcb, (float*)d_out);
}

// round 4
// speedup vs baseline: 1.1790x; 1.0641x over previous
#include <cuda_runtime.h>
#include <cstdint>

#define NIMG 256
#define IMGS_PER_BLK 8

// Layers: cin {3,344,352,686,679,1246} cout {344,352,686,679,1246,973}
// conv H=W {32,32,16,16,8,8}, pool after 1,3,5
// WINP (input words) {1,12,12,24,24,40}, WOUTP {12,12,24,24,40,32}
// Packed weight words per layer: WOUTP*9*32*WINP =
//   {3456, 41472, 82944, 165888, 276480, 368640}, cum {0,3456,44928,127872,293760,570240}

__device__ uint32_t g_bufA[(size_t)NIMG * 32 * 32 * 12];
__device__ uint32_t g_bufB[(size_t)NIMG * 32 * 32 * 12];
__device__ uint32_t g_wpk[938880];       // packed weights, all layers
__device__ int      g_wpw[41472];        // per (layer, wi, tap, cl): popc of weight row
__device__ float2   g_th[4608];          // per-channel (scale, beta - mean*scale)
__device__ uint32_t g_fcpk[10 * 16 * 32];

// ---------------------------------------------------------------------------
// Pack input x [256,3,32,32] -> bits [n][h][w][1 word]
__global__ void pack_x_kernel(const float* __restrict__ x, uint32_t* __restrict__ dst)
{
    int idx = blockIdx.x * blockDim.x + threadIdx.x;
    if (idx >= NIMG * 1024) return;
    int n = idx >> 10, pix = idx & 1023;
    const float* xb = x + (size_t)n * 3 * 1024 + pix;
    uint32_t w = 0;
    if (xb[0]    > 0.f) w |= 1u;
    if (xb[1024] > 0.f) w |= 2u;
    if (xb[2048] > 0.f) w |= 4u;
    dst[idx] = w;
}

// ---------------------------------------------------------------------------
// Pack ALL conv weights, one WARP per packed word (ballot).
// Per-layer layout: [wi][tap][32 cl][WINP q]
__global__ void pack_w_all_kernel(const float* __restrict__ w0, const float* __restrict__ w1,
                                  const float* __restrict__ w2, const float* __restrict__ w3,
                                  const float* __restrict__ w4, const float* __restrict__ w5,
                                  uint32_t* __restrict__ dst)
{
    const int cum[7]  = {0, 3456, 44928, 127872, 293760, 570240, 938880};
    const int cin[6]  = {3, 344, 352, 686, 679, 1246};
    const int cout[6] = {344, 352, 686, 679, 1246, 973};
    const int winp[6] = {1, 12, 12, 24, 24, 40};

    int warp = (blockIdx.x * blockDim.x + threadIdx.x) >> 5;
    int lane = threadIdx.x & 31;
    if (warp >= 938880) return;

    int l = 0;
#pragma unroll
    for (int i = 1; i < 6; ++i) if (warp >= cum[i]) l = i;

    const float* wsrc = (l == 0) ? w0 : (l == 1) ? w1 : (l == 2) ? w2
                       : (l == 3) ? w3 : (l == 4) ? w4 : w5;
    const int Ci = cin[l], Co = cout[l], WINP = winp[l];

    int widx = warp - cum[l];
    int q   = widx % WINP;  widx /= WINP;
    int cl  = widx & 31;    widx >>= 5;
    int tap = widx % 9;
    int wi  = widx / 9;
    int co  = wi * 32 + cl;
    int ci  = q * 32 + lane;

    float v = 0.f;
    if (co < Co && ci < Ci)
        v = wsrc[((size_t)co * Ci + ci) * 9 + tap];
    uint32_t bits = __ballot_sync(0xFFFFFFFFu, v > 0.f);
    if (lane == 0) dst[warp] = bits;
}

// ---------------------------------------------------------------------------
// Combined: per-(cout,tap) weight popcounts (reads g_wpk) + BN thresholds.
__global__ void pack_pw_th_kernel(const uint32_t* __restrict__ wpk,
                                  const float* __restrict__ p0, const float* __restrict__ p1,
                                  const float* __restrict__ p2, const float* __restrict__ p3,
                                  const float* __restrict__ p4, const float* __restrict__ p5,
                                  int* __restrict__ pw, float2* __restrict__ th)
{
    int idx = blockIdx.x * blockDim.x + threadIdx.x;
    if (idx < 41472) {
        // pw part: per-layer layout [wi][tap][32 cl]
        const int cum9[7]  = {0, 3456, 6912, 13824, 20736, 32256, 41472};
        const int woff[6]  = {0, 3456, 44928, 127872, 293760, 570240};
        const int winp[6]  = {1, 12, 12, 24, 24, 40};
        int l = 0;
#pragma unroll
        for (int i = 1; i < 6; ++i) if (idx >= cum9[i]) l = i;
        int t = idx - cum9[l];
        int cl  = t & 31;  t >>= 5;
        int tap = t % 9;
        int wi  = t / 9;
        const int WINP = winp[l];
        const uint32_t* src = wpk + woff[l] + (((size_t)wi * 9 + tap) * 32 + cl) * WINP;
        int s = 0;
        for (int q = 0; q < WINP; ++q) s += __popc(src[q]);
        pw[idx] = s;
    } else if (idx < 41472 + 4608) {
        int i2 = idx - 41472;
        const int cum[7]  = {0, 384, 768, 1536, 2304, 3584, 4608};
        const int cout[6] = {344, 352, 686, 679, 1246, 973};
        int l = 0;
#pragma unroll
        for (int i = 1; i < 6; ++i) if (i2 >= cum[i]) l = i;
        const float* p = (l == 0) ? p0 : (l == 1) ? p1 : (l == 2) ? p2
                        : (l == 3) ? p3 : (l == 4) ? p4 : p5;
        int c = i2 - cum[l];
        int Co = cout[l];
        float2 t;
        if (c < Co) {
            float gg = p[c], bb = p[Co + c], mm = p[2 * Co + c], vv = p[3 * Co + c];
            float sc = gg * rsqrtf(vv + 1e-5f);
            t.x = sc; t.y = bb - mm * sc;
        } else {
            t.x = 0.f; t.y = -1.f;
        }
        th[i2] = t;
    }
}

// Pack FC weights [10][15568] (idx = c*16 + s) -> [o][s][32 words over c]
__global__ void pack_fc_kernel(const float* __restrict__ fcw, uint32_t* __restrict__ dst)
{
    int warp = (blockIdx.x * blockDim.x + threadIdx.x) >> 5;
    int lane = threadIdx.x & 31;
    if (warp >= 10 * 16 * 32) return;
    int wi = warp & 31; int r = warp >> 5;
    int s = r & 15; int o = r >> 4;
    int c = wi * 32 + lane;
    float v = (c < 973) ? fcw[(size_t)o * 15568 + c * 16 + s] : 0.f;
    uint32_t bits = __ballot_sync(0xFFFFFFFFu, v > 0.f);
    if (lane == 0) dst[warp] = bits;
}

// ---------------------------------------------------------------------------
// Binary conv 3x3 pad 1: branch-free all-9-tap XOR/POPC against zero-filled
// halo, then epilogue correction: dot = nv*Cin - 2*D9 + 2*sum_invalid popc(w).
// Block: 256 thr = 64 pixels (8x8) x 4 groups of 8 output channels.
template <int WINP>
__global__ void __launch_bounds__(256)
bconv_kernel(const uint32_t* __restrict__ in, uint8_t* __restrict__ out,
             const uint32_t* __restrict__ wpk, const int* __restrict__ pw,
             const float2* __restrict__ th,
             int H, int W, int Cin, int WOUTP, int tilesX)
{
    extern __shared__ uint32_t sm[];
    uint32_t* sw  = sm;                           // 9*32*WINP
    int*      spw = (int*)(sm + 9 * 32 * WINP);   // 9*32
    uint32_t* sx  = sm + 9 * 32 * WINP + 288;     // 10*10*WINP
    const int tid = threadIdx.x;
    const int wi = blockIdx.y;
    const int x0 = (blockIdx.x % tilesX) * 8;
    const int y0 = (blockIdx.x / tilesX) * 8;

    const uint32_t* wsrc = wpk + (size_t)wi * (9 * 32 * WINP);
    for (int i = tid; i < 9 * 32 * WINP; i += 256) sw[i] = wsrc[i];
    if (tid < 288) spw[tid] = pw[(size_t)wi * 288 + tid];
    { int i2 = tid + 256; if (i2 < 288) spw[i2] = pw[(size_t)wi * 288 + i2]; }

    const int g  = tid >> 6;
    const int p  = tid & 63;
    const int py = p >> 3;
    const int px = p & 7;
    const int y  = y0 + py, x = x0 + px;
    const bool eT = (y == 0), eB = (y == H - 1), eL = (x == 0), eR = (x == W - 1);
    const bool edge = eT | eB | eL | eR;
    const int nv = (3 - (int)eT - (int)eB) * (3 - (int)eL - (int)eR);
    const int nvCin = nv * Cin;

    float2 t8[8];
#pragma unroll
    for (int j = 0; j < 8; ++j) t8[j] = th[wi * 32 + g * 8 + j];

    for (int it = 0; it < IMGS_PER_BLK; ++it) {
        const int n = blockIdx.z * IMGS_PER_BLK + it;
        __syncthreads();
        const uint32_t* ibase = in + (size_t)n * H * W * WINP;
        for (int i = tid; i < 100 * WINP; i += 256) {
            const int w  = i % WINP;
            const int pp = i / WINP;
            const int iy = y0 + pp / 10 - 1;
            const int ix = x0 + pp % 10 - 1;
            uint32_t v = 0u;
            if (iy >= 0 && iy < H && ix >= 0 && ix < W)
                v = ibase[((size_t)iy * W + ix) * WINP + w];
            sx[i] = v;
        }
        __syncthreads();

        int D[8];
#pragma unroll
        for (int j = 0; j < 8; ++j) D[j] = 0;

        const uint32_t* xp = &sx[(py * 10 + px) * WINP];
        const uint32_t* wp = &sw[(g * 8) * WINP];
#pragma unroll 1
        for (int ky = 0; ky < 3; ++ky) {
#pragma unroll 1
            for (int kx = 0; kx < 3; ++kx) {
                if (WINP == 1) {
                    const uint32_t xv = xp[0];
#pragma unroll
                    for (int j = 0; j < 8; ++j)
                        D[j] += __popc(xv ^ wp[j]);
                } else {
#pragma unroll
                    for (int q = 0; q < WINP / 4; ++q) {
                        const uint4 xv = *(const uint4*)(xp + q * 4);
#pragma unroll
                        for (int j = 0; j < 8; ++j) {
                            const uint4 wv = *(const uint4*)(wp + j * WINP + q * 4);
                            D[j] += (__popc(xv.x ^ wv.x) + __popc(xv.y ^ wv.y))
                                  + (__popc(xv.z ^ wv.z) + __popc(xv.w ^ wv.w));
                        }
                    }
                }
                xp += WINP;
                wp += 32 * WINP;
            }
            xp += 7 * WINP;
        }

        unsigned bytev = 0u;
#pragma unroll
        for (int j = 0; j < 8; ++j) {
            int corr = 0;
            if (edge) {
#pragma unroll
                for (int ky = 0; ky < 3; ++ky)
#pragma unroll
                    for (int kx = 0; kx < 3; ++kx) {
                        const bool inv = (eT && ky == 0) || (eB && ky == 2)
                                      || (eL && kx == 0) || (eR && kx == 2);
                        if (inv) corr += spw[(ky * 3 + kx) * 32 + g * 8 + j];
                    }
            }
            const int idot = nvCin - 2 * D[j] + 2 * corr;
            if (fmaf((float)idot, t8[j].x, t8[j].y) > 0.0f) bytev |= 1u << j;
        }
        out[(((size_t)n * H * W + (size_t)y * W + x) * WOUTP + wi) * 4 + g]
            = (uint8_t)bytev;
    }
}

// Maxpool 2x2 on packed bits == bitwise OR (BN scale > 0, monotone)
__global__ void pool_kernel(const uint32_t* __restrict__ in, uint32_t* __restrict__ out,
                            int Ho, int Wo, int WORDS, int total)
{
    int idx = blockIdx.x * blockDim.x + threadIdx.x;
    if (idx >= total) return;
    int w = idx % WORDS; int r = idx / WORDS;
    int xo = r % Wo; r /= Wo;
    int yo = r % Ho; int n = r / Ho;
    const int Wi = Wo * 2;
    size_t base = (((size_t)n * (Ho * 2) + yo * 2) * Wi + xo * 2) * WORDS + w;
    size_t rs = (size_t)Wi * WORDS;
    out[idx] = in[base] | in[base + WORDS] | in[base + rs] | in[base + rs + WORDS];
}

// Binary FC: out[n][o] = 15568 - 2*popc(x ^ w) + fcb[o]
__global__ void fc_kernel(const uint32_t* __restrict__ xb, const uint32_t* __restrict__ wb,
                          const float* __restrict__ fcb, float* __restrict__ out)
{
    int t = blockIdx.x * blockDim.x + threadIdx.x;
    if (t >= NIMG * 10) return;
    int n = t / 10, o = t - n * 10;
    const uint4* xa = (const uint4*)(xb + (size_t)n * 512);
    const uint4* wa = (const uint4*)(wb + (size_t)o * 512);
    int D = 0;
#pragma unroll 8
    for (int i = 0; i < 128; ++i) {
        uint4 a = xa[i], b = wa[i];
        D += __popc(a.x ^ b.x) + __popc(a.y ^ b.y) + __popc(a.z ^ b.z) + __popc(a.w ^ b.w);
    }
    out[t] = (float)(15568 - 2 * D) + fcb[o];
}

// ---------------------------------------------------------------------------
extern "C" void kernel_launch(void* const* d_in, const int* in_sizes, int n_in,
                              void* d_out, int out_size)
{
    static const int s_cin[6]   = {3, 344, 352, 686, 679, 1246};
    static const int s_H[6]     = {32, 32, 16, 16, 8, 8};
    static const int s_winp[6]  = {1, 12, 12, 24, 24, 40};
    static const int s_woutp[6] = {12, 12, 24, 24, 40, 32};
    static const size_t s_woff[6] = {0, 3456, 44928, 127872, 293760, 570240};
    static const size_t s_toff[6] = {0, 384, 768, 1536, 2304, 3584};

    const long long szw[6] = {344LL*3*9, 352LL*344*9, 686LL*352*9,
                              679LL*686*9, 1246LL*679*9, 973LL*1246*9};
    const long long szp[6] = {4LL*344, 4LL*352, 4LL*686, 4LL*679, 4LL*1246, 4LL*973};
    auto find = [&](long long s) -> const void* {
        for (int i = 0; i < n_in; ++i)
            if ((long long)in_sizes[i] == s) return d_in[i];
        return (const void*)0;
    };
    const float* x   = (const float*)find(256LL * 3 * 32 * 32);
    const float* fcw = (const float*)find(10LL * 15568);
    const float* fcb = (const float*)find(10);
    const float* w[6]; const float* p[6];
    for (int i = 0; i < 6; ++i) {
        w[i] = (const float*)find(szw[i]);
        p[i] = (const float*)find(szp[i]);
    }
    if (!x || !fcw || !fcb) return;

    void *pA, *pB, *pW, *pPW, *pT, *pF;
    cudaGetSymbolAddress(&pA, g_bufA);
    cudaGetSymbolAddress(&pB, g_bufB);
    cudaGetSymbolAddress(&pW, g_wpk);
    cudaGetSymbolAddress(&pPW, g_wpw);
    cudaGetSymbolAddress(&pT, g_th);
    cudaGetSymbolAddress(&pF, g_fcpk);
    uint32_t* bufA = (uint32_t*)pA;
    uint32_t* bufB = (uint32_t*)pB;
    uint32_t* wpk  = (uint32_t*)pW;
    int*      wpw  = (int*)pPW;
    float2*   th   = (float2*)pT;
    uint32_t* fcpk = (uint32_t*)pF;

    auto smemFor = [](int winp) { return (size_t)(9 * 32 * winp + 288 + 100 * winp) * 4; };
    cudaFuncSetAttribute(bconv_kernel<40>, cudaFuncAttributeMaxDynamicSharedMemorySize, (int)smemFor(40));
    cudaFuncSetAttribute(bconv_kernel<24>, cudaFuncAttributeMaxDynamicSharedMemorySize, (int)smemFor(24));

    // --- pack phase: 4 launches; conv0 is launch #4, conv1 is #5 (ncu -s 5) ---
    pack_x_kernel<<<(NIMG * 1024 + 255) / 256, 256>>>(x, bufA);
    pack_w_all_kernel<<<(938880 * 32 + 255) / 256, 256>>>(w[0], w[1], w[2], w[3], w[4], w[5], wpk);
    pack_pw_th_kernel<<<(41472 + 4608 + 255) / 256, 256>>>(wpk, p[0], p[1], p[2], p[3], p[4], p[5], wpw, th);
    pack_fc_kernel<<<(10 * 16 * 32 * 32 + 255) / 256, 256>>>(fcw, fcpk);

    // --- conv stack ---
    auto conv = [&](int l, const uint32_t* src, uint32_t* dst) {
        int H = s_H[l], W = H;
        int WINP = s_winp[l], WOUTP = s_woutp[l], Cin = s_cin[l];
        int tilesX = (W + 7) / 8;
        dim3 grid((unsigned)(((H + 7) / 8) * tilesX), (unsigned)WOUTP,
                  (unsigned)(NIMG / IMGS_PER_BLK));
        size_t smem = smemFor(WINP);
        uint8_t* ob = (uint8_t*)dst;
        const uint32_t* wb = wpk + s_woff[l];
        const int* pwb = wpw + s_toff[l] * 9;
        const float2* tb = th + s_toff[l];
        switch (WINP) {
            case 1:  bconv_kernel<1><<<grid, 256, smem>>>(src, ob, wb, pwb, tb, H, W, Cin, WOUTP, tilesX); break;
            case 12: bconv_kernel<12><<<grid, 256, smem>>>(src, ob, wb, pwb, tb, H, W, Cin, WOUTP, tilesX); break;
            case 24: bconv_kernel<24><<<grid, 256, smem>>>(src, ob, wb, pwb, tb, H, W, Cin, WOUTP, tilesX); break;
            case 40: bconv_kernel<40><<<grid, 256, smem>>>(src, ob, wb, pwb, tb, H, W, Cin, WOUTP, tilesX); break;
        }
    };

    conv(0, bufA, bufB);                                    // B: [32,32,12]
    conv(1, bufB, bufA);                                    // A: conv-space [32,32,12]
    {   int tot = NIMG * 16 * 16 * 12;
        pool_kernel<<<(tot + 255) / 256, 256>>>(bufA, bufB, 16, 16, 12, tot); }  // B: [16,16,12]
    conv(2, bufB, bufA);                                    // A: [16,16,24]
    conv(3, bufA, bufB);                                    // B: conv-space [16,16,24]
    {   int tot = NIMG * 8 * 8 * 24;
        pool_kernel<<<(tot + 255) / 256, 256>>>(bufB, bufA, 8, 8, 24, tot); }    // A: [8,8,24]
    conv(4, bufA, bufB);                                    // B: [8,8,40]
    conv(5, bufB, bufA);                                    // A: conv-space [8,8,32]
    {   int tot = NIMG * 4 * 4 * 32;
        pool_kernel<<<(tot + 255) / 256, 256>>>(bufA, bufB, 4, 4, 32, tot); }    // B: [4,4,32]

    // --- FC ---
    fc_kernel<<<10, 256>>>(bufB, fcpk, fcb, (float*)d_out);
}

// round 5
// speedup vs baseline: 1.4965x; 1.2694x over previous
#include <cuda_runtime.h>
#include <cstdint>

#define NIMG 256
#define IMGS_PER_BLK 8

// Layers: cin {3,344,352,686,679,1246} cout {344,352,686,679,1246,973}
// conv H=W {32,32,16,16,8,8}, pool after 1,3,5
// WINP {1,12,12,24,24,40}, WOUTP {12,12,24,24,40,32}
// Packed weight words/layer: WOUTP*9*32*WINP -> cum {0,3456,44928,127872,293760,570240}, tot 938880

__device__ uint32_t g_bufA[(size_t)NIMG * 32 * 32 * 12];
__device__ uint32_t g_bufB[(size_t)NIMG * 32 * 32 * 12];
__device__ uint32_t g_wpk[938880];
__device__ int      g_wpw[41472];        // per (layer, wi, tap, cl): popc of weight row
__device__ float2   g_th[4608];          // per-channel (scale, beta - mean*scale)
__device__ uint32_t g_fcpk[10 * 16 * 32];

// ---------------------------------------------------------------------------
// Merged pack: x activations (first 262144 threads) + all conv weights (warp ballot).
__global__ void pack_xw_kernel(const float* __restrict__ x,
                               const float* __restrict__ w0, const float* __restrict__ w1,
                               const float* __restrict__ w2, const float* __restrict__ w3,
                               const float* __restrict__ w4, const float* __restrict__ w5,
                               uint32_t* __restrict__ dstx, uint32_t* __restrict__ dstw)
{
    int idx = blockIdx.x * blockDim.x + threadIdx.x;
    if (idx < NIMG * 1024) {
        int n = idx >> 10, pix = idx & 1023;
        const float* xb = x + (size_t)n * 3 * 1024 + pix;
        uint32_t w = 0;
        if (xb[0]    > 0.f) w |= 1u;
        if (xb[1024] > 0.f) w |= 2u;
        if (xb[2048] > 0.f) w |= 4u;
        dstx[idx] = w;
        return;
    }
    // weight pack: warp-aligned region (262144 = 8192 warps)
    const int cum[7]  = {0, 3456, 44928, 127872, 293760, 570240, 938880};
    const int cin[6]  = {3, 344, 352, 686, 679, 1246};
    const int cout[6] = {344, 352, 686, 679, 1246, 973};
    const int winp[6] = {1, 12, 12, 24, 24, 40};

    int warp = (idx >> 5) - 8192;
    int lane = idx & 31;
    if (warp >= 938880) return;

    int l = 0;
#pragma unroll
    for (int i = 1; i < 6; ++i) if (warp >= cum[i]) l = i;

    const float* wsrc = (l == 0) ? w0 : (l == 1) ? w1 : (l == 2) ? w2
                       : (l == 3) ? w3 : (l == 4) ? w4 : w5;
    const int Ci = cin[l], Co = cout[l], WINP = winp[l];

    int widx = warp - cum[l];
    int q   = widx % WINP;  widx /= WINP;
    int cl  = widx & 31;    widx >>= 5;
    int tap = widx % 9;
    int wi  = widx / 9;
    int co  = wi * 32 + cl;
    int ci  = q * 32 + lane;

    float v = 0.f;
    if (co < Co && ci < Ci)
        v = wsrc[((size_t)co * Ci + ci) * 9 + tap];
    uint32_t bits = __ballot_sync(0xFFFFFFFFu, v > 0.f);
    if (lane == 0) dstw[warp] = bits;
}

// ---------------------------------------------------------------------------
// Merged pack: FC weights (warp ballot, first 163840 threads), then per-tap
// weight popcounts (reads g_wpk), then BN thresholds.
__global__ void pack_misc_kernel(const uint32_t* __restrict__ wpk,
                                 const float* __restrict__ fcw,
                                 const float* __restrict__ p0, const float* __restrict__ p1,
                                 const float* __restrict__ p2, const float* __restrict__ p3,
                                 const float* __restrict__ p4, const float* __restrict__ p5,
                                 int* __restrict__ pw, float2* __restrict__ th,
                                 uint32_t* __restrict__ fcpk)
{
    int idx = blockIdx.x * blockDim.x + threadIdx.x;
    if (idx < 163840) {
        int warp = idx >> 5;
        int lane = idx & 31;
        int wi = warp & 31; int r = warp >> 5;
        int s = r & 15; int o = r >> 4;
        int c = wi * 32 + lane;
        float v = (c < 973) ? fcw[(size_t)o * 15568 + c * 16 + s] : 0.f;
        uint32_t bits = __ballot_sync(0xFFFFFFFFu, v > 0.f);
        if (lane == 0) fcpk[warp] = bits;
    } else if (idx < 163840 + 41472) {
        int i1 = idx - 163840;
        const int cum9[7]  = {0, 3456, 6912, 13824, 20736, 32256, 41472};
        const int woff[6]  = {0, 3456, 44928, 127872, 293760, 570240};
        const int winp[6]  = {1, 12, 12, 24, 24, 40};
        int l = 0;
#pragma unroll
        for (int i = 1; i < 6; ++i) if (i1 >= cum9[i]) l = i;
        int t = i1 - cum9[l];
        int cl  = t & 31;  t >>= 5;
        int tap = t % 9;
        int wi  = t / 9;
        const int WINP = winp[l];
        const uint32_t* src = wpk + woff[l] + (((size_t)wi * 9 + tap) * 32 + cl) * WINP;
        int s = 0;
        for (int q = 0; q < WINP; ++q) s += __popc(src[q]);
        pw[i1] = s;
    } else if (idx < 163840 + 41472 + 4608) {
        int i2 = idx - 163840 - 41472;
        const int cum[7]  = {0, 384, 768, 1536, 2304, 3584, 4608};
        const int cout[6] = {344, 352, 686, 679, 1246, 973};
        int l = 0;
#pragma unroll
        for (int i = 1; i < 6; ++i) if (i2 >= cum[i]) l = i;
        const float* p = (l == 0) ? p0 : (l == 1) ? p1 : (l == 2) ? p2
                        : (l == 3) ? p3 : (l == 4) ? p4 : p5;
        int c = i2 - cum[l];
        int Co = cout[l];
        float2 t;
        if (c < Co) {
            float gg = p[c], bb = p[Co + c], mm = p[2 * Co + c], vv = p[3 * Co + c];
            float sc = gg * rsqrtf(vv + 1e-5f);
            t.x = sc; t.y = bb - mm * sc;
        } else {
            t.x = 0.f; t.y = -1.f;
        }
        th[i2] = t;
    }
}

// ---------------------------------------------------------------------------
// Binary conv 3x3 pad 1, branch-free all-9-taps + edge correction.
// CSA popcount compression: per 3 words, popc(a)+popc(b)+popc(c) =
//   popc(a^b^c) + 2*popc(maj(a,b,c))  -> 2 POPC instead of 3 (POPC is quarter-rate).
// Block: 256 thr = 64 pixels (8x8) x 4 groups of 8 output channels.
template <int WINP>
__global__ void __launch_bounds__(256)
bconv_kernel(const uint32_t* __restrict__ in, uint8_t* __restrict__ out,
             const uint32_t* __restrict__ wpk, const int* __restrict__ pw,
             const float2* __restrict__ th,
             int H, int W, int Cin, int WOUTP, int tilesX)
{
    extern __shared__ uint32_t sm[];
    uint32_t* sw  = sm;                           // 9*32*WINP
    int*      spw = (int*)(sm + 9 * 32 * WINP);   // 9*32
    uint32_t* sx  = sm + 9 * 32 * WINP + 288;     // 10*10*WINP
    const int tid = threadIdx.x;
    const int wi = blockIdx.y;
    const int x0 = (blockIdx.x % tilesX) * 8;
    const int y0 = (blockIdx.x / tilesX) * 8;

    const uint32_t* wsrc = wpk + (size_t)wi * (9 * 32 * WINP);
    for (int i = tid; i < 9 * 32 * WINP; i += 256) sw[i] = wsrc[i];
    if (tid < 288) spw[tid] = pw[(size_t)wi * 288 + tid];
    { int i2 = tid + 256; if (i2 < 288) spw[i2] = pw[(size_t)wi * 288 + i2]; }

    const int g  = tid >> 6;
    const int p  = tid & 63;
    const int py = p >> 3;
    const int px = p & 7;
    const int y  = y0 + py, x = x0 + px;
    const bool eT = (y == 0), eB = (y == H - 1), eL = (x == 0), eR = (x == W - 1);
    const bool edge = eT | eB | eL | eR;
    const int nv = (3 - (int)eT - (int)eB) * (3 - (int)eL - (int)eR);
    const int nvCin = nv * Cin;

    float2 t8[8];
#pragma unroll
    for (int j = 0; j < 8; ++j) t8[j] = th[wi * 32 + g * 8 + j];

    for (int it = 0; it < IMGS_PER_BLK; ++it) {
        const int n = blockIdx.z * IMGS_PER_BLK + it;
        __syncthreads();
        const uint32_t* ibase = in + (size_t)n * H * W * WINP;
        for (int i = tid; i < 100 * WINP; i += 256) {
            const int w  = i % WINP;
            const int pp = i / WINP;
            const int iy = y0 + pp / 10 - 1;
            const int ix = x0 + pp % 10 - 1;
            uint32_t v = 0u;
            if (iy >= 0 && iy < H && ix >= 0 && ix < W)
                v = ibase[((size_t)iy * W + ix) * WINP + w];
            sx[i] = v;
        }
        __syncthreads();

        int D1[8], D2[8];
#pragma unroll
        for (int j = 0; j < 8; ++j) { D1[j] = 0; D2[j] = 0; }

        const uint32_t* xp = &sx[(py * 10 + px) * WINP];
        const uint32_t* wp = &sw[(g * 8) * WINP];
#pragma unroll 1
        for (int ky = 0; ky < 3; ++ky) {
#pragma unroll 1
            for (int kx = 0; kx < 3; ++kx) {
                if (WINP == 1) {
                    const uint32_t xv = xp[0];
#pragma unroll
                    for (int j = 0; j < 8; ++j)
                        D1[j] += __popc(xv ^ wp[j]);
                } else {
#pragma unroll
                    for (int t3 = 0; t3 < WINP / 12; ++t3) {
                        const uint4 x0v = *(const uint4*)(xp + t3 * 12);
                        const uint4 x1v = *(const uint4*)(xp + t3 * 12 + 4);
                        const uint4 x2v = *(const uint4*)(xp + t3 * 12 + 8);
#pragma unroll
                        for (int j = 0; j < 8; ++j) {
                            const uint32_t* wj = wp + j * WINP + t3 * 12;
                            const uint4 w0v = *(const uint4*)(wj);
                            const uint4 w1v = *(const uint4*)(wj + 4);
                            const uint4 w2v = *(const uint4*)(wj + 8);
                            uint32_t a, b, c, s, m;
                            int p1, p2;
                            a = x0v.x ^ w0v.x; b = x1v.x ^ w1v.x; c = x2v.x ^ w2v.x;
                            s = a ^ b ^ c; m = (a & b) | (c & (a | b));
                            p1 = __popc(s); p2 = __popc(m);
                            a = x0v.y ^ w0v.y; b = x1v.y ^ w1v.y; c = x2v.y ^ w2v.y;
                            s = a ^ b ^ c; m = (a & b) | (c & (a | b));
                            p1 += __popc(s); p2 += __popc(m);
                            a = x0v.z ^ w0v.z; b = x1v.z ^ w1v.z; c = x2v.z ^ w2v.z;
                            s = a ^ b ^ c; m = (a & b) | (c & (a | b));
                            p1 += __popc(s); p2 += __popc(m);
                            a = x0v.w ^ w0v.w; b = x1v.w ^ w1v.w; c = x2v.w ^ w2v.w;
                            s = a ^ b ^ c; m = (a & b) | (c & (a | b));
                            p1 += __popc(s); p2 += __popc(m);
                            D1[j] += p1; D2[j] += p2;
                        }
                    }
                    if (WINP - (WINP / 12) * 12 == 4) {   // WINP=40 leftover uint4
                        const uint4 xv = *(const uint4*)(xp + (WINP / 12) * 12);
#pragma unroll
                        for (int j = 0; j < 8; ++j) {
                            const uint4 wv = *(const uint4*)(wp + j * WINP + (WINP / 12) * 12);
                            D1[j] += (__popc(xv.x ^ wv.x) + __popc(xv.y ^ wv.y))
                                   + (__popc(xv.z ^ wv.z) + __popc(xv.w ^ wv.w));
                        }
                    }
                }
                xp += WINP;
                wp += 32 * WINP;
            }
            xp += 7 * WINP;
        }

        unsigned bytev = 0u;
#pragma unroll
        for (int j = 0; j < 8; ++j) {
            int corr = 0;
            if (edge) {
#pragma unroll
                for (int ky = 0; ky < 3; ++ky)
#pragma unroll
                    for (int kx = 0; kx < 3; ++kx) {
                        const bool inv = (eT && ky == 0) || (eB && ky == 2)
                                      || (eL && kx == 0) || (eR && kx == 2);
                        if (inv) corr += spw[(ky * 3 + kx) * 32 + g * 8 + j];
                    }
            }
            const int D = D1[j] + 2 * D2[j];
            const int idot = nvCin - 2 * D + 2 * corr;
            if (fmaf((float)idot, t8[j].x, t8[j].y) > 0.0f) bytev |= 1u << j;
        }
        out[(((size_t)n * H * W + (size_t)y * W + x) * WOUTP + wi) * 4 + g]
            = (uint8_t)bytev;
    }
}

// Maxpool 2x2 on packed bits == bitwise OR (BN scale > 0, monotone)
__global__ void pool_kernel(const uint32_t* __restrict__ in, uint32_t* __restrict__ out,
                            int Ho, int Wo, int WORDS, int total)
{
    int idx = blockIdx.x * blockDim.x + threadIdx.x;
    if (idx >= total) return;
    int w = idx % WORDS; int r = idx / WORDS;
    int xo = r % Wo; r /= Wo;
    int yo = r % Ho; int n = r / Ho;
    const int Wi = Wo * 2;
    size_t base = (((size_t)n * (Ho * 2) + yo * 2) * Wi + xo * 2) * WORDS + w;
    size_t rs = (size_t)Wi * WORDS;
    out[idx] = in[base] | in[base + WORDS] | in[base + rs] | in[base + rs + WORDS];
}

// Binary FC: out[n][o] = 15568 - 2*popc(x ^ w) + fcb[o]
__global__ void fc_kernel(const uint32_t* __restrict__ xb, const uint32_t* __restrict__ wb,
                          const float* __restrict__ fcb, float* __restrict__ out)
{
    int t = blockIdx.x * blockDim.x + threadIdx.x;
    if (t >= NIMG * 10) return;
    int n = t / 10, o = t - n * 10;
    const uint4* xa = (const uint4*)(xb + (size_t)n * 512);
    const uint4* wa = (const uint4*)(wb + (size_t)o * 512);
    int D = 0;
#pragma unroll 8
    for (int i = 0; i < 128; ++i) {
        uint4 a = xa[i], b = wa[i];
        D += __popc(a.x ^ b.x) + __popc(a.y ^ b.y) + __popc(a.z ^ b.z) + __popc(a.w ^ b.w);
    }
    out[t] = (float)(15568 - 2 * D) + fcb[o];
}

// ---------------------------------------------------------------------------
extern "C" void kernel_launch(void* const* d_in, const int* in_sizes, int n_in,
                              void* d_out, int out_size)
{
    static const int s_cin[6]   = {3, 344, 352, 686, 679, 1246};
    static const int s_H[6]     = {32, 32, 16, 16, 8, 8};
    static const int s_winp[6]  = {1, 12, 12, 24, 24, 40};
    static const int s_woutp[6] = {12, 12, 24, 24, 40, 32};
    static const size_t s_woff[6] = {0, 3456, 44928, 127872, 293760, 570240};
    static const size_t s_toff[6] = {0, 384, 768, 1536, 2304, 3584};

    const long long szw[6] = {344LL*3*9, 352LL*344*9, 686LL*352*9,
                              679LL*686*9, 1246LL*679*9, 973LL*1246*9};
    const long long szp[6] = {4LL*344, 4LL*352, 4LL*686, 4LL*679, 4LL*1246, 4LL*973};
    auto find = [&](long long s) -> const void* {
        for (int i = 0; i < n_in; ++i)
            if ((long long)in_sizes[i] == s) return d_in[i];
        return (const void*)0;
    };
    const float* x   = (const float*)find(256LL * 3 * 32 * 32);
    const float* fcw = (const float*)find(10LL * 15568);
    const float* fcb = (const float*)find(10);
    const float* w[6]; const float* p[6];
    for (int i = 0; i < 6; ++i) {
        w[i] = (const float*)find(szw[i]);
        p[i] = (const float*)find(szp[i]);
    }
    if (!x || !fcw || !fcb) return;

    void *pA, *pB, *pW, *pPW, *pT, *pF;
    cudaGetSymbolAddress(&pA, g_bufA);
    cudaGetSymbolAddress(&pB, g_bufB);
    cudaGetSymbolAddress(&pW, g_wpk);
    cudaGetSymbolAddress(&pPW, g_wpw);
    cudaGetSymbolAddress(&pT, g_th);
    cudaGetSymbolAddress(&pF, g_fcpk);
    uint32_t* bufA = (uint32_t*)pA;
    uint32_t* bufB = (uint32_t*)pB;
    uint32_t* wpk  = (uint32_t*)pW;
    int*      wpw  = (int*)pPW;
    float2*   th   = (float2*)pT;
    uint32_t* fcpk = (uint32_t*)pF;

    auto smemFor = [](int winp) { return (size_t)(9 * 32 * winp + 288 + 100 * winp) * 4; };
    cudaFuncSetAttribute(bconv_kernel<40>, cudaFuncAttributeMaxDynamicSharedMemorySize, (int)smemFor(40));
    cudaFuncSetAttribute(bconv_kernel<24>, cudaFuncAttributeMaxDynamicSharedMemorySize, (int)smemFor(24));

    // --- pack phase: 2 launches (so ncu -s 5 lands on conv1 at our-index 3) ---
    {
        int tot = NIMG * 1024 + 938880 * 32;
        pack_xw_kernel<<<(tot + 255) / 256, 256>>>(x, w[0], w[1], w[2], w[3], w[4], w[5],
                                                   bufA, wpk);
    }
    {
        int tot = 163840 + 41472 + 4608;
        pack_misc_kernel<<<(tot + 255) / 256, 256>>>(wpk, fcw, p[0], p[1], p[2], p[3], p[4], p[5],
                                                     wpw, th, fcpk);
    }

    // --- conv stack ---
    auto conv = [&](int l, const uint32_t* src, uint32_t* dst) {
        int H = s_H[l], W = H;
        int WINP = s_winp[l], WOUTP = s_woutp[l], Cin = s_cin[l];
        int tilesX = (W + 7) / 8;
        dim3 grid((unsigned)(((H + 7) / 8) * tilesX), (unsigned)WOUTP,
                  (unsigned)(NIMG / IMGS_PER_BLK));
        size_t smem = smemFor(WINP);
        uint8_t* ob = (uint8_t*)dst;
        const uint32_t* wb = wpk + s_woff[l];
        const int* pwb = wpw + s_toff[l] * 9;
        const float2* tb = th + s_toff[l];
        switch (WINP) {
            case 1:  bconv_kernel<1><<<grid, 256, smem>>>(src, ob, wb, pwb, tb, H, W, Cin, WOUTP, tilesX); break;
            case 12: bconv_kernel<12><<<grid, 256, smem>>>(src, ob, wb, pwb, tb, H, W, Cin, WOUTP, tilesX); break;
            case 24: bconv_kernel<24><<<grid, 256, smem>>>(src, ob, wb, pwb, tb, H, W, Cin, WOUTP, tilesX); break;
            case 40: bconv_kernel<40><<<grid, 256, smem>>>(src, ob, wb, pwb, tb, H, W, Cin, WOUTP, tilesX); break;
        }
    };

    conv(0, bufA, bufB);                                    // B: [32,32,12]
    conv(1, bufB, bufA);                                    // A: conv-space [32,32,12]
    {   int tot = NIMG * 16 * 16 * 12;
        pool_kernel<<<(tot + 255) / 256, 256>>>(bufA, bufB, 16, 16, 12, tot); }  // B: [16,16,12]
    conv(2, bufB, bufA);                                    // A: [16,16,24]
    conv(3, bufA, bufB);                                    // B: conv-space [16,16,24]
    {   int tot = NIMG * 8 * 8 * 24;
        pool_kernel<<<(tot + 255) / 256, 256>>>(bufB, bufA, 8, 8, 24, tot); }    // A: [8,8,24]
    conv(4, bufA, bufB);                                    // B: [8,8,40]
    conv(5, bufB, bufA);                                    // A: conv-space [8,8,32]
    {   int tot = NIMG * 4 * 4 * 32;
        pool_kernel<<<(tot + 255) / 256, 256>>>(bufA, bufB, 4, 4, 32, tot); }    // B: [4,4,32]

    // --- FC ---
    fc_kernel<<<10, 256>>>(bufB, fcpk, fcb, (float*)d_out);
}